// round 14
// baseline (speedup 1.0000x reference)
#include <cuda_runtime.h>
#include <cuda_bf16.h>
#include <math.h>

typedef __nv_bfloat16 bf16;
#define TOTAL 16777216
#define PI_F 3.14159265358979f
#define DCT_SMEM 55296
#define GEMM_SMEM 37888

__device__ bf16  g_Ac16[64*64];
__device__ bf16  g_AcT16[64*64];
__device__ bf16  g_Ak16[512*512];
__device__ bf16  g_AkI16[512*512];
__device__ bf16  g_T16[TOTAL];
__device__ bf16  g_D16[TOTAL];
__device__ bf16  g_M1b[4*128*512];
__device__ bf16  g_H1pre[32*128*4096];
__device__ bf16  g_H1[32*128*4096];
__device__ bf16  g_H2[32*128*4096];
__device__ bf16  g_OUTS16[TOTAL];
__device__ bf16  g_W1b[4*128*512];
__device__ bf16  g_W2b[4*128*1152];
__device__ bf16  g_W3b[4*128*128];
__device__ unsigned g_hist[1024];
__device__ unsigned g_prefix[4];
__device__ unsigned g_remain[4];
__device__ unsigned g_thrbits[4];
__device__ unsigned char g_tflags[4096];

__device__ __forceinline__ unsigned packbf(float a, float b) {
    return (unsigned)__bfloat16_as_ushort(__float2bfloat16(a))
         | ((unsigned)__bfloat16_as_ushort(__float2bfloat16(b)) << 16);
}
__device__ __forceinline__ float fexp(float v) {
    float t = v * 1.44269504f;
    int i = (int)t;
    float f = t - (float)i;
    float p = 1.8775767e-3f;
    p = fmaf(p, f, 8.9893397e-3f);
    p = fmaf(p, f, 5.5826318e-2f);
    p = fmaf(p, f, 2.4015361e-1f);
    p = fmaf(p, f, 6.9315307e-1f);
    p = fmaf(p, f, 9.9999989e-1f);
    return p * __int_as_float((i + 127) << 23);
}
__device__ __forceinline__ unsigned smem_u32(const void* p) {
    return (unsigned)__cvta_generic_to_shared(p);
}

__global__ void k_init() {
    int t = threadIdx.x;
    if (t < 4) { g_prefix[t] = 0u; g_remain[t] = (unsigned)(TOTAL >> (2 + 2*t)); }
    for (int i = t; i < 1024; i += blockDim.x) g_hist[i] = 0u;
}

__global__ void k_build_mats() {
    int tid = blockIdx.x * blockDim.x + threadIdx.x;
    if (tid < 512*512) {
        int k = tid >> 9, c = tid & 511;
        float v = cosf((float)k * ((float)c + 0.5f) * (PI_F/512.0f)) * 0.0625f;
        if (k == 0) v *= 0.70710678f;
        g_Ak16[k*512 + c]  = __float2bfloat16(v);
        g_AkI16[c*512 + k] = __float2bfloat16(v);
    }
    if (tid < 4096) {
        int k = tid >> 6, n = tid & 63;
        float v = cosf((float)k * ((float)n + 0.5f) * (PI_F/64.0f)) * 0.1767767f;
        if (k == 0) v *= 0.70710678f;
        bf16 f = __float2bfloat16(v);
        g_Ac16[k*64 + n]  = f;
        g_AcT16[n*64 + k] = f;
    }
}

__global__ void k_cvt_all(const float* __restrict__ W1, const float* __restrict__ W2,
                          const float* __restrict__ W3) {
    int i = blockIdx.x * blockDim.x + threadIdx.x;
    if (i < 262144) {
        g_W1b[i] = __float2bfloat16(W1[i]);
    } else if (i < 262144 + 589824) {
        int q = i - 262144;
        int tap = q % 9;
        int r = q / 9;
        int c = r & 127; r >>= 7;
        int o = r & 127; int j = r >> 7;
        g_W2b[((j*128 + o)*1152) + tap*128 + c] = __float2bfloat16(W2[q]);
    } else if (i < 262144 + 589824 + 65536) {
        int q = i - 262144 - 589824;
        g_W3b[q] = __float2bfloat16(W3[q]);
    }
}

// ---------------- tensor-core fused 64x64 two-sided DCT ----------------
template<int FP32IN, int BIASRELU>
__global__ __launch_bounds__(256) void k_dct64_tc(
    const void* __restrict__ vin, bf16* __restrict__ out,
    const bf16* __restrict__ A1g, const bf16* __restrict__ A2g,
    const float* __restrict__ bias)
{
    extern __shared__ bf16 sm[];
    const int tid = threadIdx.x;
    #pragma unroll
    for (int it = 0; it < 4; it++) {
        int f = it*256 + tid;
        int mat = f >> 9, wf = f & 511;
        int row = wf >> 3, colb = (wf & 7) * 8;
        uint4 v = *(const uint4*)((mat ? A2g : A1g) + row*64 + colb);
        *(uint4*)&sm[mat*4608 + row*72 + colb] = v;
    }
    if (FP32IN) {
        const float* xin = (const float*)vin;
        #pragma unroll
        for (int it = 0; it < 8; it++) {
            int f = it*256 + tid;
            int s = f >> 10, wf = f & 1023;
            int row = wf >> 4, colf = (wf & 15) * 4;
            float4 v = *(const float4*)(xin + (size_t)(blockIdx.x*2 + s)*4096 + row*64 + colf);
            *(uint2*)&sm[9216 + s*4608 + row*72 + colf] =
                make_uint2(packbf(v.x, v.y), packbf(v.z, v.w));
        }
    } else {
        const bf16* yin = (const bf16*)vin;
        #pragma unroll
        for (int it = 0; it < 4; it++) {
            int f = it*256 + tid;
            int s = f >> 9, wf = f & 511;
            int row = wf >> 3, colb = (wf & 7) * 8;
            uint4 v = *(const uint4*)(yin + (size_t)(blockIdx.x*2 + s)*4096 + row*64 + colb);
            *(uint4*)&sm[9216 + s*4608 + row*72 + colb] = v;
        }
    }
    __syncthreads();

    const int warp = tid >> 5, lane = tid & 31;
    const int s = warp >> 2, wrow = (warp & 3) * 16;
    const int slice = blockIdx.x*2 + s;
    float bi = 0.f;
    if (BIASRELU) bi = bias[(slice >> 10)*128 + (slice & 127)];
    bf16* mX = sm + 9216 + s*4608;
    bf16* mQ = sm + 18432 + s*4608;
    const int quad = lane >> 3, qr = lane & 7;
    const int a_moff = (quad & 1)*8 + qr;
    const int a_koff = (quad >> 1)*8;
    const int b_koff = lane & 15;
    const int g = lane >> 2, t4 = lane & 3;

    float acc[8][4];
    unsigned afA[4][4];

    #pragma unroll
    for (int i = 0; i < 8; i++) { acc[i][0]=0.f; acc[i][1]=0.f; acc[i][2]=0.f; acc[i][3]=0.f; }
    #pragma unroll
    for (int kk = 0; kk < 4; kk++) {
        unsigned addr = smem_u32(&sm[(wrow + a_moff)*72 + kk*16 + a_koff]);
        asm volatile("ldmatrix.sync.aligned.m8n8.x4.shared.b16 {%0,%1,%2,%3}, [%4];"
            : "=r"(afA[kk][0]), "=r"(afA[kk][1]), "=r"(afA[kk][2]), "=r"(afA[kk][3]) : "r"(addr));
    }
    #pragma unroll
    for (int kk = 0; kk < 4; kk++)
        #pragma unroll
        for (int nt = 0; nt < 8; nt++) {
            unsigned b0, b1;
            unsigned addr = smem_u32(&mX[(kk*16 + b_koff)*72 + nt*8]);
            asm volatile("ldmatrix.sync.aligned.m8n8.x2.trans.shared.b16 {%0,%1}, [%2];"
                : "=r"(b0), "=r"(b1) : "r"(addr));
            float* c = acc[nt];
            asm volatile(
                "mma.sync.aligned.m16n8k16.row.col.f32.bf16.bf16.f32 "
                "{%0,%1,%2,%3}, {%4,%5,%6,%7}, {%8,%9}, {%0,%1,%2,%3};"
                : "+f"(c[0]), "+f"(c[1]), "+f"(c[2]), "+f"(c[3])
                : "r"(afA[kk][0]), "r"(afA[kk][1]), "r"(afA[kk][2]), "r"(afA[kk][3]),
                  "r"(b0), "r"(b1));
        }
    #pragma unroll
    for (int nt = 0; nt < 8; nt++)
        #pragma unroll
        for (int h = 0; h < 2; h++) {
            int row = wrow + g + h*8, col = nt*8 + t4*2;
            *(unsigned*)&mQ[row*72 + col] = packbf(acc[nt][h*2], acc[nt][h*2+1]);
        }
    __syncwarp();

    #pragma unroll
    for (int i = 0; i < 8; i++) { acc[i][0]=0.f; acc[i][1]=0.f; acc[i][2]=0.f; acc[i][3]=0.f; }
    #pragma unroll
    for (int kk = 0; kk < 4; kk++) {
        unsigned addr = smem_u32(&mQ[(wrow + a_moff)*72 + kk*16 + a_koff]);
        asm volatile("ldmatrix.sync.aligned.m8n8.x4.shared.b16 {%0,%1,%2,%3}, [%4];"
            : "=r"(afA[kk][0]), "=r"(afA[kk][1]), "=r"(afA[kk][2]), "=r"(afA[kk][3]) : "r"(addr));
    }
    #pragma unroll
    for (int kk = 0; kk < 4; kk++)
        #pragma unroll
        for (int nt = 0; nt < 8; nt++) {
            unsigned b0, b1;
            unsigned addr = smem_u32(&sm[4608 + (kk*16 + b_koff)*72 + nt*8]);
            asm volatile("ldmatrix.sync.aligned.m8n8.x2.trans.shared.b16 {%0,%1}, [%2];"
                : "=r"(b0), "=r"(b1) : "r"(addr));
            float* c = acc[nt];
            asm volatile(
                "mma.sync.aligned.m16n8k16.row.col.f32.bf16.bf16.f32 "
                "{%0,%1,%2,%3}, {%4,%5,%6,%7}, {%8,%9}, {%0,%1,%2,%3};"
                : "+f"(c[0]), "+f"(c[1]), "+f"(c[2]), "+f"(c[3])
                : "r"(afA[kk][0]), "r"(afA[kk][1]), "r"(afA[kk][2]), "r"(afA[kk][3]),
                  "r"(b0), "r"(b1));
        }
    bf16* dst = out + (size_t)slice*4096;
    #pragma unroll
    for (int nt = 0; nt < 8; nt++)
        #pragma unroll
        for (int h = 0; h < 2; h++) {
            int row = wrow + g + h*8, col = nt*8 + t4*2;
            float v0 = acc[nt][h*2], v1 = acc[nt][h*2+1];
            if (BIASRELU) { v0 = fmaxf(v0 + bi, 0.f); v1 = fmaxf(v1 + bi, 0.f); }
            *(unsigned*)&dst[row*64 + col] = packbf(v0, v1);
        }
}

// ---------------- bf16 mma.sync GEMM: 128 threads, 4 warps of 64x64 ----------------
template<int MASKED, int RELU, int IM2COL, int ZDIV, int BMOD8>
__global__ __launch_bounds__(128) void k_bgemm(
    const bf16* __restrict__ Abase, long strideAj,
    const bf16* __restrict__ Bbase, long strideB, int ldb,
    bf16* __restrict__ Cbase, long strideC, int ldc,
    int K, const float* __restrict__ bias)
{
    extern __shared__ bf16 dsm[];
    bf16* sA = dsm;              // 2 x 128*40
    bf16* sB = dsm + 10240;      // 2 x 32*136
    __shared__ unsigned char s_klist[16];
    __shared__ int s_kn;
    const int tid = threadIdx.x;
    const int warp = tid >> 5, lane = tid & 31;
    const int z = blockIdx.z;
    const int jj = z >> ZDIV;
    const int zb = BMOD8 ? (z & 7) : z;
    const bf16* __restrict__ A = Abase + (long)jj * strideAj;
    const bf16* __restrict__ B = Bbase + (long)zb * strideB;
    const int m0 = blockIdx.y << 7, n0 = blockIdx.x << 7;
    const int wm = (warp >> 1) * 64;
    const int wn = (warp & 1) * 64;
    const unsigned thr = MASKED ? g_thrbits[jj] : 0u;

    if (MASKED) {
        if (tid == 0) {
            int cnt = 0;
            int base = zb*512 + (n0 >> 7);
            for (int kt = 0; kt < 16; kt++)
                if (g_tflags[base + kt*32] & (1u << jj)) s_klist[cnt++] = (unsigned char)kt;
            s_kn = cnt;
        }
        __syncthreads();
    }

    const int quad = lane >> 3, qr = lane & 7;
    const int a_moff = (quad & 1) * 8 + qr;
    const int a_koff = (quad >> 1) * 8;
    const int b_koff = lane & 15;
    const int b_nhalf = (lane >> 4) * 8;

    const int b_kr = tid >> 2;            // 0..31
    const int b_ng = (tid & 3) * 32;      // 0,32,64,96

    float acc[32][4];
    #pragma unroll
    for (int i = 0; i < 32; i++) { acc[i][0]=0.f; acc[i][1]=0.f; acc[i][2]=0.f; acc[i][3]=0.f; }

    uint4 rA[4], rB[4];

    auto loadTile = [&](int k0) {
        #pragma unroll
        for (int i = 0; i < 4; i++)
            rA[i] = *(const uint4*)&A[(size_t)(m0 + tid) * K + k0 + i*8];
        if (!IM2COL) {
            int krow = k0 + b_kr;
            const bf16* bp = &B[(size_t)krow * ldb + n0 + b_ng];
            #pragma unroll
            for (int i = 0; i < 4; i++) rB[i] = *(const uint4*)(bp + i*8);
            if (MASKED) {
                unsigned short* ss = (unsigned short*)rB;
                #pragma unroll
                for (int e = 0; e < 32; e++)
                    if ((unsigned)(ss[e] & 0x7fff) < thr) ss[e] = 0;
            }
        } else {
            int k = k0 + b_kr;
            int tap = k >> 7;
            int c = k & 127;
            int t3 = tap / 3;
            int dy = 2*t3 - 2;
            int dx = 2*(tap - 3*t3) - 2;
            int mn0 = n0 + b_ng;
            int m = mn0 >> 6, n = mn0 & 63;        // n in {0,32}
            int mp = m + dy;
            bool mok = ((unsigned)mp < 64u);
            const bf16* row = &B[(size_t)c * 4096 + mp * 64];
            unsigned u[16];
            unsigned e = 0;
            if (mok) {
                #pragma unroll
                for (int i = 0; i < 4; i++) {
                    uint4 v = *(const uint4*)&row[n + i*8];
                    u[i*4+0] = v.x; u[i*4+1] = v.y; u[i*4+2] = v.z; u[i*4+3] = v.w;
                }
                if (dx == 2)       { if (n + 32 < 64) e = *(const unsigned*)&row[n + 32]; }
                else if (dx == -2) { if (n > 0)       e = *(const unsigned*)&row[n - 2]; }
            } else {
                #pragma unroll
                for (int i = 0; i < 16; i++) u[i] = 0u;
            }
            unsigned o[16];
            if (dx == 0) {
                #pragma unroll
                for (int i = 0; i < 16; i++) o[i] = u[i];
            } else if (dx == 2) {
                #pragma unroll
                for (int i = 0; i < 15; i++) o[i] = u[i+1];
                o[15] = e;
            } else {
                o[0] = e;
                #pragma unroll
                for (int i = 1; i < 16; i++) o[i] = u[i-1];
            }
            #pragma unroll
            for (int i = 0; i < 4; i++)
                rB[i] = make_uint4(o[i*4+0], o[i*4+1], o[i*4+2], o[i*4+3]);
        }
    };
    auto storeTile = [&](int buf) {
        #pragma unroll
        for (int i = 0; i < 4; i++)
            *(uint4*)&sA[buf*5120 + tid*40 + i*8] = rA[i];
        #pragma unroll
        for (int i = 0; i < 4; i++)
            *(uint4*)&sB[buf*4352 + b_kr*136 + b_ng + i*8] = rB[i];
    };
    auto mmaStep = [&](const bf16* aT, const bf16* bT, int kk) {
        unsigned af[4][4], bfr[4][4];
        #pragma unroll
        for (int mt = 0; mt < 4; mt++) {
            unsigned addr = smem_u32(&aT[(wm + mt*16 + a_moff)*40 + kk + a_koff]);
            asm volatile("ldmatrix.sync.aligned.m8n8.x4.shared.b16 {%0,%1,%2,%3}, [%4];"
                : "=r"(af[mt][0]), "=r"(af[mt][1]), "=r"(af[mt][2]), "=r"(af[mt][3])
                : "r"(addr));
        }
        #pragma unroll
        for (int p = 0; p < 4; p++) {
            unsigned addr = smem_u32(&bT[(kk + b_koff)*136 + wn + p*16 + b_nhalf]);
            asm volatile("ldmatrix.sync.aligned.m8n8.x4.trans.shared.b16 {%0,%1,%2,%3}, [%4];"
                : "=r"(bfr[p][0]), "=r"(bfr[p][1]), "=r"(bfr[p][2]), "=r"(bfr[p][3])
                : "r"(addr));
        }
        #pragma unroll
        for (int mt = 0; mt < 4; mt++)
            #pragma unroll
            for (int p = 0; p < 4; p++) {
                float* c0 = acc[mt*8 + p*2];
                asm volatile(
                    "mma.sync.aligned.m16n8k16.row.col.f32.bf16.bf16.f32 "
                    "{%0,%1,%2,%3}, {%4,%5,%6,%7}, {%8,%9}, {%0,%1,%2,%3};"
                    : "+f"(c0[0]), "+f"(c0[1]), "+f"(c0[2]), "+f"(c0[3])
                    : "r"(af[mt][0]), "r"(af[mt][1]), "r"(af[mt][2]), "r"(af[mt][3]),
                      "r"(bfr[p][0]), "r"(bfr[p][1]));
                float* c1 = acc[mt*8 + p*2 + 1];
                asm volatile(
                    "mma.sync.aligned.m16n8k16.row.col.f32.bf16.bf16.f32 "
                    "{%0,%1,%2,%3}, {%4,%5,%6,%7}, {%8,%9}, {%0,%1,%2,%3};"
                    : "+f"(c1[0]), "+f"(c1[1]), "+f"(c1[2]), "+f"(c1[3])
                    : "r"(af[mt][0]), "r"(af[mt][1]), "r"(af[mt][2]), "r"(af[mt][3]),
                      "r"(bfr[p][2]), "r"(bfr[p][3]));
            }
    };

    const int ntiles = MASKED ? s_kn : (K >> 5);
    if (ntiles > 0) {
        loadTile(MASKED ? ((int)s_klist[0] << 5) : 0);
        storeTile(0);
        __syncthreads();
        for (int t = 0; t < ntiles; t++) {
            const int buf = t & 1;
            if (t + 1 < ntiles)
                loadTile(MASKED ? ((int)s_klist[t + 1] << 5) : ((t + 1) << 5));
            mmaStep(sA + buf*5120, sB + buf*4352, 0);
            mmaStep(sA + buf*5120, sB + buf*4352, 16);
            if (t + 1 < ntiles) storeTile(buf ^ 1);
            __syncthreads();
        }
    }

    const int g = lane >> 2, t = lane & 3;
    bf16* C = Cbase + (long)z * strideC;
    #pragma unroll
    for (int mt = 0; mt < 4; mt++)
        #pragma unroll
        for (int half = 0; half < 2; half++) {
            int mrow = m0 + wm + mt*16 + g + half*8;
            float bi = RELU ? bias[jj*128 + ((wm + mt*16 + g + half*8) & 127)] : 0.f;
            #pragma unroll
            for (int nt = 0; nt < 8; nt++) {
                float v0 = acc[mt*8 + nt][half*2 + 0] + bi;
                float v1 = acc[mt*8 + nt][half*2 + 1] + bi;
                if (RELU) { v0 = fmaxf(v0, 0.f); v1 = fmaxf(v1, 0.f); }
                int col = n0 + wn + nt*8 + t*2;
                *(unsigned*)&C[(size_t)mrow * ldc + col] = packbf(v0, v1);
            }
        }
}

// ---------------- per-tile max |D16| -> activity flags ----------------
__global__ __launch_bounds__(256) void k_tilemax() {
    int tile = blockIdx.x;
    int nt = tile & 31, r = tile >> 5;
    int kt = r & 15, b = r >> 4;
    const bf16* base = g_D16 + (size_t)b*2097152 + (size_t)kt*32*4096 + nt*128;
    int tid = threadIdx.x;
    int kr = tid >> 3, c0 = (tid & 7) * 16;
    const uint4* p = (const uint4*)(base + (size_t)kr*4096 + c0);
    uint4 u0 = p[0], u1 = p[1];
    unsigned ws[8] = {u0.x, u0.y, u0.z, u0.w, u1.x, u1.y, u1.z, u1.w};
    unsigned mx = 0;
    #pragma unroll
    for (int e = 0; e < 8; e++) {
        unsigned lo = ws[e] & 0x7fffu, hi = (ws[e] >> 16) & 0x7fffu;
        mx = max(mx, max(lo, hi));
    }
    mx = __reduce_max_sync(0xffffffffu, mx);
    __shared__ unsigned sm[8];
    if ((tid & 31) == 0) sm[tid >> 5] = mx;
    __syncthreads();
    if (tid == 0) {
        unsigned m = 0;
        #pragma unroll
        for (int w = 0; w < 8; w++) m = max(m, sm[w]);
        unsigned flags = 0;
        #pragma unroll
        for (int j = 0; j < 4; j++)
            if (m >= g_thrbits[j]) flags |= (1u << j);
        g_tflags[tile] = (unsigned char)flags;
    }
}

// ---------------- bf16 radix select ----------------
__global__ __launch_bounds__(256) void k_histA() {
    __shared__ unsigned sh[256];
    int tid = threadIdx.x;
    sh[tid] = 0u;
    __syncthreads();
    const uint4* __restrict__ src = (const uint4*)g_D16;
    int idx = blockIdx.x * 256 + tid;
    const int stride = gridDim.x * 256;
    const int lane = tid & 31;
    for (int i = idx; i < TOTAL/8; i += stride) {
        uint4 u = src[i];
        unsigned w[4] = {u.x, u.y, u.z, u.w};
        #pragma unroll
        for (int e = 0; e < 4; e++) {
            unsigned lo = (w[e] & 0x7fffu) >> 7;
            unsigned hi = ((w[e] >> 16) & 0x7fffu) >> 7;
            unsigned mm = __match_any_sync(0xffffffffu, lo);
            if (lane == __ffs(mm) - 1) atomicAdd(&sh[lo], (unsigned)__popc(mm));
            mm = __match_any_sync(0xffffffffu, hi);
            if (lane == __ffs(mm) - 1) atomicAdd(&sh[hi], (unsigned)__popc(mm));
        }
    }
    __syncthreads();
    if (sh[tid]) atomicAdd(&g_hist[tid], sh[tid]);
}

__global__ void k_scanA() {
    int j = threadIdx.x;
    if (j < 4) {
        unsigned krem = g_remain[j];
        unsigned cum = 0; int chosen = 0;
        for (int b = 255; b >= 0; b--) {
            unsigned hv = g_hist[b];
            if (cum + hv >= krem) { chosen = b; break; }
            cum += hv;
        }
        g_remain[j] = krem - cum;
        g_prefix[j] = (unsigned)chosen;
    }
    __syncthreads();
    for (int i = threadIdx.x; i < 1024; i += blockDim.x) g_hist[i] = 0u;
}

__global__ __launch_bounds__(256) void k_histB() {
    __shared__ unsigned sh[4][128];
    int tid = threadIdx.x;
    for (int i = tid; i < 512; i += 256) ((unsigned*)sh)[i] = 0u;
    __syncthreads();
    unsigned ph[4];
    #pragma unroll
    for (int j = 0; j < 4; j++) ph[j] = g_prefix[j];
    const uint4* __restrict__ src = (const uint4*)g_D16;
    int idx = blockIdx.x * 256 + tid;
    const int stride = gridDim.x * 256;
    for (int i = idx; i < TOTAL/8; i += stride) {
        uint4 u = src[i];
        unsigned w[4] = {u.x, u.y, u.z, u.w};
        #pragma unroll
        for (int e = 0; e < 4; e++) {
            #pragma unroll
            for (int h = 0; h < 2; h++) {
                unsigned mag = ((h ? (w[e] >> 16) : w[e]) & 0x7fffu);
                unsigned hi = mag >> 7, lo = mag & 127u;
                #pragma unroll
                for (int j = 0; j < 4; j++)
                    if (hi == ph[j]) atomicAdd(&sh[j][lo], 1u);
            }
        }
    }
    __syncthreads();
    for (int i = tid; i < 512; i += 256) {
        unsigned v = ((unsigned*)sh)[i];
        if (v) atomicAdd(&g_hist[i], v);
    }
}

__global__ void k_scanB() {
    int j = threadIdx.x;
    if (j < 4) {
        unsigned krem = g_remain[j];
        const unsigned* h = &g_hist[j*128];
        unsigned cum = 0; int chosen = 0;
        for (int b = 127; b >= 0; b--) {
            unsigned hv = h[b];
            if (cum + hv >= krem) { chosen = b; break; }
            cum += hv;
        }
        g_thrbits[j] = (g_prefix[j] << 7) | (unsigned)chosen;
    }
}

__global__ __launch_bounds__(256) void k_final(const float* __restrict__ x, float* __restrict__ out) {
    int t = blockIdx.x * 256 + threadIdx.x;
    if (t >= 8*4096) return;
    int b = t >> 12, mn = t & 4095;
    const int obase = b * 524288 + mn;
    const size_t xbase = (size_t)b * 2097152 + mn;
    float s = 0.f;
    #pragma unroll 4
    for (int c = 0; c < 512; c++) {
        float v = __bfloat162float(g_OUTS16[(c >> 7) * 4194304 + obase + (c & 127) * 4096]);
        s += fexp(v);
    }
    float inv = 1.f / s;
    #pragma unroll 4
    for (int c = 0; c < 512; c++) {
        float v = __bfloat162float(g_OUTS16[(c >> 7) * 4194304 + obase + (c & 127) * 4096]);
        float w = fexp(v) * inv;
        float xv = x[xbase + (size_t)c * 4096];
        out[xbase + (size_t)c * 4096] = fmaf(xv, w, xv);
    }
}

extern "C" void kernel_launch(void* const* d_in, const int* in_sizes, int n_in,
                              void* d_out, int out_size) {
    const float* x  = (const float*)d_in[0];
    const float* W1 = (const float*)d_in[1];
    const float* b1 = (const float*)d_in[2];
    const float* W2 = (const float*)d_in[3];
    const float* b2 = (const float*)d_in[4];
    const float* W3 = (const float*)d_in[5];
    const float* b3 = (const float*)d_in[6];
    float* out = (float*)d_out;

    bf16 *gT16, *gD16, *gM1b, *gH1pre, *gH1, *gH2, *gOUTS16;
    bf16 *gAk16, *gAkI, *gAc16, *gAcT16, *gW1b, *gW2b, *gW3b;
    cudaGetSymbolAddress((void**)&gT16, g_T16);
    cudaGetSymbolAddress((void**)&gD16, g_D16);
    cudaGetSymbolAddress((void**)&gM1b, g_M1b);
    cudaGetSymbolAddress((void**)&gH1pre, g_H1pre);
    cudaGetSymbolAddress((void**)&gH1, g_H1);
    cudaGetSymbolAddress((void**)&gH2, g_H2);
    cudaGetSymbolAddress((void**)&gOUTS16, g_OUTS16);
    cudaGetSymbolAddress((void**)&gAk16, g_Ak16);
    cudaGetSymbolAddress((void**)&gAkI, g_AkI16);
    cudaGetSymbolAddress((void**)&gAc16, g_Ac16);
    cudaGetSymbolAddress((void**)&gAcT16, g_AcT16);
    cudaGetSymbolAddress((void**)&gW1b, g_W1b);
    cudaGetSymbolAddress((void**)&gW2b, g_W2b);
    cudaGetSymbolAddress((void**)&gW3b, g_W3b);

    cudaFuncSetAttribute(k_dct64_tc<1,0>, cudaFuncAttributeMaxDynamicSharedMemorySize, DCT_SMEM);
    cudaFuncSetAttribute(k_dct64_tc<0,1>, cudaFuncAttributeMaxDynamicSharedMemorySize, DCT_SMEM);
    cudaFuncSetAttribute(k_bgemm<0,0,0,5,1>, cudaFuncAttributeMaxDynamicSharedMemorySize, GEMM_SMEM);
    cudaFuncSetAttribute(k_bgemm<0,0,0,0,0>, cudaFuncAttributeMaxDynamicSharedMemorySize, GEMM_SMEM);
    cudaFuncSetAttribute(k_bgemm<1,0,0,3,1>, cudaFuncAttributeMaxDynamicSharedMemorySize, GEMM_SMEM);
    cudaFuncSetAttribute(k_bgemm<0,1,1,3,0>, cudaFuncAttributeMaxDynamicSharedMemorySize, GEMM_SMEM);
    cudaFuncSetAttribute(k_bgemm<0,1,0,3,0>, cudaFuncAttributeMaxDynamicSharedMemorySize, GEMM_SMEM);

    k_init<<<1, 256>>>();
    k_build_mats<<<1024, 256>>>();

    // forward: MN DCT then C-DCT -> D16 (fwd GEMM at ncu slot 3)
    k_dct64_tc<1,0><<<2048, 256, DCT_SMEM>>>(x, gT16, gAc16, gAcT16, nullptr);
    k_bgemm<0,0,0,5,1><<<dim3(32,4,8), 128, GEMM_SMEM>>>(gAk16, 0L, gT16, 2097152L, 4096, gD16, 2097152L, 4096, 512, nullptr);

    k_cvt_all<<<3584, 256>>>(W1, W2, W3);
    // M1[j] = W1[j] @ AkI
    k_bgemm<0,0,0,0,0><<<dim3(4,1,4), 128, GEMM_SMEM>>>(gW1b, 65536L, gAkI, 0L, 512, gM1b, 65536L, 512, 512, nullptr);

    // 2-pass bf16 radix select + tile flags
    k_histA<<<512, 256>>>(); k_scanA<<<1, 256>>>();
    k_histB<<<512, 256>>>(); k_scanB<<<1, 4>>>();
    k_tilemax<<<4096, 256>>>();

    // masked inverse-C fused with conv1 -> H1pre ; spatial inverse + bias1/relu -> H1
    k_bgemm<1,0,0,3,1><<<dim3(32,1,32), 128, GEMM_SMEM>>>(gM1b, 65536L, gD16, 2097152L, 4096, gH1pre, 524288L, 4096, 512, nullptr);
    k_dct64_tc<0,1><<<2048, 256, DCT_SMEM>>>(gH1pre, gH1, gAcT16, gAc16, b1);
    // conv2 (im2col fused) and conv3
    k_bgemm<0,1,1,3,0><<<dim3(32,1,32), 128, GEMM_SMEM>>>(gW2b, 147456L, gH1, 524288L, 4096, gH2, 524288L, 4096, 1152, b2);
    k_bgemm<0,1,0,3,0><<<dim3(32,1,32), 128, GEMM_SMEM>>>(gW3b, 16384L, gH2, 524288L, 4096, gOUTS16, 524288L, 4096, 128, b3);

    k_final<<<128, 256>>>(x, out);
}

// round 15
// speedup vs baseline: 1.3569x; 1.3569x over previous
#include <cuda_runtime.h>
#include <cuda_bf16.h>
#include <math.h>

typedef __nv_bfloat16 bf16;
#define TOTAL 16777216
#define PI_F 3.14159265358979f
#define DCT_SMEM 55296
#define FINAL_SMEM 65536

__device__ bf16  g_Ac16[64*64];
__device__ bf16  g_AcT16[64*64];
__device__ bf16  g_Ak16[512*512];
__device__ bf16  g_AkI16[512*512];
__device__ bf16  g_T16[TOTAL];
__device__ bf16  g_D16[TOTAL];
__device__ bf16  g_M1b[4*128*512];
__device__ bf16  g_H1pre[32*128*4096];
__device__ bf16  g_H1[32*128*4096];
__device__ bf16  g_H2[32*128*4096];
__device__ bf16  g_OUTS16[TOTAL];
__device__ bf16  g_W1b[4*128*512];
__device__ bf16  g_W2b[4*128*1152];
__device__ bf16  g_W3b[4*128*128];
__device__ unsigned g_hist[1024];
__device__ unsigned g_prefix[4];
__device__ unsigned g_remain[4];
__device__ unsigned g_thrbits[4];
__device__ unsigned char g_tflags[4096];

__device__ __forceinline__ unsigned packbf(float a, float b) {
    return (unsigned)__bfloat16_as_ushort(__float2bfloat16(a))
         | ((unsigned)__bfloat16_as_ushort(__float2bfloat16(b)) << 16);
}
__device__ __forceinline__ float fexp(float v) {
    float t = v * 1.44269504f;
    int i = (int)t;
    float f = t - (float)i;
    float p = 1.8775767e-3f;
    p = fmaf(p, f, 8.9893397e-3f);
    p = fmaf(p, f, 5.5826318e-2f);
    p = fmaf(p, f, 2.4015361e-1f);
    p = fmaf(p, f, 6.9315307e-1f);
    p = fmaf(p, f, 9.9999989e-1f);
    return p * __int_as_float((i + 127) << 23);
}
__device__ __forceinline__ unsigned smem_u32(const void* p) {
    return (unsigned)__cvta_generic_to_shared(p);
}

__global__ void k_init() {
    int t = threadIdx.x;
    if (t < 4) { g_prefix[t] = 0u; g_remain[t] = (unsigned)(TOTAL >> (2 + 2*t)); }
    for (int i = t; i < 1024; i += blockDim.x) g_hist[i] = 0u;
}

__global__ void k_build_mats() {
    int tid = blockIdx.x * blockDim.x + threadIdx.x;
    if (tid < 512*512) {
        int k = tid >> 9, c = tid & 511;
        float v = cosf((float)k * ((float)c + 0.5f) * (PI_F/512.0f)) * 0.0625f;
        if (k == 0) v *= 0.70710678f;
        g_Ak16[k*512 + c]  = __float2bfloat16(v);
        g_AkI16[c*512 + k] = __float2bfloat16(v);
    }
    if (tid < 4096) {
        int k = tid >> 6, n = tid & 63;
        float v = cosf((float)k * ((float)n + 0.5f) * (PI_F/64.0f)) * 0.1767767f;
        if (k == 0) v *= 0.70710678f;
        bf16 f = __float2bfloat16(v);
        g_Ac16[k*64 + n]  = f;
        g_AcT16[n*64 + k] = f;
    }
}

__global__ void k_cvt_all(const float* __restrict__ W1, const float* __restrict__ W2,
                          const float* __restrict__ W3) {
    int i = blockIdx.x * blockDim.x + threadIdx.x;
    if (i < 262144) {
        g_W1b[i] = __float2bfloat16(W1[i]);
    } else if (i < 262144 + 589824) {
        int q = i - 262144;
        int tap = q % 9;
        int r = q / 9;
        int c = r & 127; r >>= 7;
        int o = r & 127; int j = r >> 7;
        g_W2b[((j*128 + o)*1152) + tap*128 + c] = __float2bfloat16(W2[q]);
    } else if (i < 262144 + 589824 + 65536) {
        int q = i - 262144 - 589824;
        g_W3b[q] = __float2bfloat16(W3[q]);
    }
}

// ---------------- tensor-core fused 64x64 two-sided DCT ----------------
template<int FP32IN, int BIASRELU>
__global__ __launch_bounds__(256) void k_dct64_tc(
    const void* __restrict__ vin, bf16* __restrict__ out,
    const bf16* __restrict__ A1g, const bf16* __restrict__ A2g,
    const float* __restrict__ bias)
{
    extern __shared__ bf16 sm[];
    const int tid = threadIdx.x;
    #pragma unroll
    for (int it = 0; it < 4; it++) {
        int f = it*256 + tid;
        int mat = f >> 9, wf = f & 511;
        int row = wf >> 3, colb = (wf & 7) * 8;
        uint4 v = *(const uint4*)((mat ? A2g : A1g) + row*64 + colb);
        *(uint4*)&sm[mat*4608 + row*72 + colb] = v;
    }
    if (FP32IN) {
        const float* xin = (const float*)vin;
        #pragma unroll
        for (int it = 0; it < 8; it++) {
            int f = it*256 + tid;
            int s = f >> 10, wf = f & 1023;
            int row = wf >> 4, colf = (wf & 15) * 4;
            float4 v = *(const float4*)(xin + (size_t)(blockIdx.x*2 + s)*4096 + row*64 + colf);
            *(uint2*)&sm[9216 + s*4608 + row*72 + colf] =
                make_uint2(packbf(v.x, v.y), packbf(v.z, v.w));
        }
    } else {
        const bf16* yin = (const bf16*)vin;
        #pragma unroll
        for (int it = 0; it < 4; it++) {
            int f = it*256 + tid;
            int s = f >> 9, wf = f & 511;
            int row = wf >> 3, colb = (wf & 7) * 8;
            uint4 v = *(const uint4*)(yin + (size_t)(blockIdx.x*2 + s)*4096 + row*64 + colb);
            *(uint4*)&sm[9216 + s*4608 + row*72 + colb] = v;
        }
    }
    __syncthreads();

    const int warp = tid >> 5, lane = tid & 31;
    const int s = warp >> 2, wrow = (warp & 3) * 16;
    const int slice = blockIdx.x*2 + s;
    float bi = 0.f;
    if (BIASRELU) bi = bias[(slice >> 10)*128 + (slice & 127)];
    bf16* mX = sm + 9216 + s*4608;
    bf16* mQ = sm + 18432 + s*4608;
    const int quad = lane >> 3, qr = lane & 7;
    const int a_moff = (quad & 1)*8 + qr;
    const int a_koff = (quad >> 1)*8;
    const int b_koff = lane & 15;
    const int g = lane >> 2, t4 = lane & 3;

    float acc[8][4];
    unsigned afA[4][4];

    #pragma unroll
    for (int i = 0; i < 8; i++) { acc[i][0]=0.f; acc[i][1]=0.f; acc[i][2]=0.f; acc[i][3]=0.f; }
    #pragma unroll
    for (int kk = 0; kk < 4; kk++) {
        unsigned addr = smem_u32(&sm[(wrow + a_moff)*72 + kk*16 + a_koff]);
        asm volatile("ldmatrix.sync.aligned.m8n8.x4.shared.b16 {%0,%1,%2,%3}, [%4];"
            : "=r"(afA[kk][0]), "=r"(afA[kk][1]), "=r"(afA[kk][2]), "=r"(afA[kk][3]) : "r"(addr));
    }
    #pragma unroll
    for (int kk = 0; kk < 4; kk++)
        #pragma unroll
        for (int nt = 0; nt < 8; nt++) {
            unsigned b0, b1;
            unsigned addr = smem_u32(&mX[(kk*16 + b_koff)*72 + nt*8]);
            asm volatile("ldmatrix.sync.aligned.m8n8.x2.trans.shared.b16 {%0,%1}, [%2];"
                : "=r"(b0), "=r"(b1) : "r"(addr));
            float* c = acc[nt];
            asm volatile(
                "mma.sync.aligned.m16n8k16.row.col.f32.bf16.bf16.f32 "
                "{%0,%1,%2,%3}, {%4,%5,%6,%7}, {%8,%9}, {%0,%1,%2,%3};"
                : "+f"(c[0]), "+f"(c[1]), "+f"(c[2]), "+f"(c[3])
                : "r"(afA[kk][0]), "r"(afA[kk][1]), "r"(afA[kk][2]), "r"(afA[kk][3]),
                  "r"(b0), "r"(b1));
        }
    #pragma unroll
    for (int nt = 0; nt < 8; nt++)
        #pragma unroll
        for (int h = 0; h < 2; h++) {
            int row = wrow + g + h*8, col = nt*8 + t4*2;
            *(unsigned*)&mQ[row*72 + col] = packbf(acc[nt][h*2], acc[nt][h*2+1]);
        }
    __syncwarp();

    #pragma unroll
    for (int i = 0; i < 8; i++) { acc[i][0]=0.f; acc[i][1]=0.f; acc[i][2]=0.f; acc[i][3]=0.f; }
    #pragma unroll
    for (int kk = 0; kk < 4; kk++) {
        unsigned addr = smem_u32(&mQ[(wrow + a_moff)*72 + kk*16 + a_koff]);
        asm volatile("ldmatrix.sync.aligned.m8n8.x4.shared.b16 {%0,%1,%2,%3}, [%4];"
            : "=r"(afA[kk][0]), "=r"(afA[kk][1]), "=r"(afA[kk][2]), "=r"(afA[kk][3]) : "r"(addr));
    }
    #pragma unroll
    for (int kk = 0; kk < 4; kk++)
        #pragma unroll
        for (int nt = 0; nt < 8; nt++) {
            unsigned b0, b1;
            unsigned addr = smem_u32(&sm[4608 + (kk*16 + b_koff)*72 + nt*8]);
            asm volatile("ldmatrix.sync.aligned.m8n8.x2.trans.shared.b16 {%0,%1}, [%2];"
                : "=r"(b0), "=r"(b1) : "r"(addr));
            float* c = acc[nt];
            asm volatile(
                "mma.sync.aligned.m16n8k16.row.col.f32.bf16.bf16.f32 "
                "{%0,%1,%2,%3}, {%4,%5,%6,%7}, {%8,%9}, {%0,%1,%2,%3};"
                : "+f"(c[0]), "+f"(c[1]), "+f"(c[2]), "+f"(c[3])
                : "r"(afA[kk][0]), "r"(afA[kk][1]), "r"(afA[kk][2]), "r"(afA[kk][3]),
                  "r"(b0), "r"(b1));
        }
    bf16* dst = out + (size_t)slice*4096;
    #pragma unroll
    for (int nt = 0; nt < 8; nt++)
        #pragma unroll
        for (int h = 0; h < 2; h++) {
            int row = wrow + g + h*8, col = nt*8 + t4*2;
            float v0 = acc[nt][h*2], v1 = acc[nt][h*2+1];
            if (BIASRELU) { v0 = fmaxf(v0 + bi, 0.f); v1 = fmaxf(v1 + bi, 0.f); }
            *(unsigned*)&dst[row*64 + col] = packbf(v0, v1);
        }
}

// ---------------- bf16 mma.sync GEMM (round-12 proven config) ----------------
template<int MASKED, int RELU, int IM2COL, int ZDIV, int BMOD8>
__global__ __launch_bounds__(256) void k_bgemm(
    const bf16* __restrict__ Abase, long strideAj,
    const bf16* __restrict__ Bbase, long strideB, int ldb,
    bf16* __restrict__ Cbase, long strideC, int ldc,
    int K, const float* __restrict__ bias)
{
    __shared__ bf16 sA[2][128*40];
    __shared__ bf16 sB[2][32*136];
    __shared__ unsigned char s_klist[16];
    __shared__ int s_kn;
    const int tid = threadIdx.x;
    const int warp = tid >> 5, lane = tid & 31;
    const int z = blockIdx.z;
    const int jj = z >> ZDIV;
    const int zb = BMOD8 ? (z & 7) : z;
    const bf16* __restrict__ A = Abase + (long)jj * strideAj;
    const bf16* __restrict__ B = Bbase + (long)zb * strideB;
    const int m0 = blockIdx.y << 7, n0 = blockIdx.x << 7;
    const int wm = (warp >> 2) * 64;
    const int wn = (warp & 3) * 32;
    const unsigned thr = MASKED ? g_thrbits[jj] : 0u;

    if (MASKED) {
        if (tid == 0) {
            int cnt = 0;
            int base = zb*512 + (n0 >> 7);
            for (int kt = 0; kt < 16; kt++)
                if (g_tflags[base + kt*32] & (1u << jj)) s_klist[cnt++] = (unsigned char)kt;
            s_kn = cnt;
        }
        __syncthreads();
    }

    const int quad = lane >> 3, qr = lane & 7;
    const int a_moff = (quad & 1) * 8 + qr;
    const int a_koff = (quad >> 1) * 8;
    const int b_koff = lane & 15;

    const int a_r = tid >> 2;
    const int a_kg = (tid & 3) * 8;
    const int b_kr = tid >> 3;
    const int b_ng = (tid & 7) * 16;

    float acc[16][4];
    #pragma unroll
    for (int i = 0; i < 16; i++) { acc[i][0]=0.f; acc[i][1]=0.f; acc[i][2]=0.f; acc[i][3]=0.f; }

    uint4 rA0, rA1, rB0, rB1;

    auto loadTile = [&](int k0) {
        rA0 = *(const uint4*)&A[(size_t)(m0 + a_r) * K + k0 + a_kg];
        rA1 = *(const uint4*)&A[(size_t)(m0 + a_r + 64) * K + k0 + a_kg];
        if (!IM2COL) {
            int krow = k0 + b_kr;
            const bf16* bp = &B[(size_t)krow * ldb + n0 + b_ng];
            rB0 = *(const uint4*)bp;
            rB1 = *(const uint4*)(bp + 8);
            if (MASKED) {
                unsigned short* s0 = (unsigned short*)&rB0;
                unsigned short* s1 = (unsigned short*)&rB1;
                #pragma unroll
                for (int e = 0; e < 8; e++) {
                    if ((unsigned)(s0[e] & 0x7fff) < thr) s0[e] = 0;
                    if ((unsigned)(s1[e] & 0x7fff) < thr) s1[e] = 0;
                }
            }
        } else {
            int k = k0 + b_kr;
            int tap = k >> 7;
            int c = k & 127;
            int t3 = tap / 3;
            int dy = 2*t3 - 2;
            int dx = 2*(tap - 3*t3) - 2;
            int mn0 = n0 + b_ng;
            int m = mn0 >> 6, n = mn0 & 63;
            int mp = m + dy;
            bool mok = ((unsigned)mp < 64u);
            const bf16* row = &B[(size_t)c * 4096 + mp * 64];
            uint4 a0 = make_uint4(0,0,0,0), a1 = make_uint4(0,0,0,0);
            unsigned e = 0;
            if (mok) {
                a0 = *(const uint4*)&row[n];
                a1 = *(const uint4*)&row[n + 8];
                if (dx == 2)       { if (n + 16 < 64) e = *(const unsigned*)&row[n + 16]; }
                else if (dx == -2) { if (n > 0)       e = *(const unsigned*)&row[n - 2]; }
            }
            if (dx == 0)      { rB0 = a0; rB1 = a1; }
            else if (dx == 2) { rB0 = make_uint4(a0.y, a0.z, a0.w, a1.x);
                                rB1 = make_uint4(a1.y, a1.z, a1.w, e); }
            else              { rB0 = make_uint4(e, a0.x, a0.y, a0.z);
                                rB1 = make_uint4(a0.w, a1.x, a1.y, a1.z); }
        }
    };
    auto storeTile = [&](int buf) {
        *(uint4*)&sA[buf][a_r*40 + a_kg]        = rA0;
        *(uint4*)&sA[buf][(a_r + 64)*40 + a_kg] = rA1;
        *(uint4*)&sB[buf][b_kr*136 + b_ng]      = rB0;
        *(uint4*)&sB[buf][b_kr*136 + b_ng + 8]  = rB1;
    };

    const int ntiles = MASKED ? s_kn : (K >> 5);
    if (ntiles > 0) {
        loadTile(MASKED ? ((int)s_klist[0] << 5) : 0);
        storeTile(0);
        __syncthreads();
        for (int t = 0; t < ntiles; t++) {
            const int buf = t & 1;
            if (t + 1 < ntiles)
                loadTile(MASKED ? ((int)s_klist[t + 1] << 5) : ((t + 1) << 5));
            #pragma unroll
            for (int kk = 0; kk < 32; kk += 16) {
                unsigned af[4][4], bfr[4][2];
                #pragma unroll
                for (int mt = 0; mt < 4; mt++) {
                    unsigned addr = smem_u32(&sA[buf][(wm + mt*16 + a_moff)*40 + kk + a_koff]);
                    asm volatile("ldmatrix.sync.aligned.m8n8.x4.shared.b16 {%0,%1,%2,%3}, [%4];"
                        : "=r"(af[mt][0]), "=r"(af[mt][1]), "=r"(af[mt][2]), "=r"(af[mt][3])
                        : "r"(addr));
                }
                #pragma unroll
                for (int nt = 0; nt < 4; nt++) {
                    unsigned addr = smem_u32(&sB[buf][(kk + b_koff)*136 + wn + nt*8]);
                    asm volatile("ldmatrix.sync.aligned.m8n8.x2.trans.shared.b16 {%0,%1}, [%2];"
                        : "=r"(bfr[nt][0]), "=r"(bfr[nt][1]) : "r"(addr));
                }
                #pragma unroll
                for (int mt = 0; mt < 4; mt++)
                    #pragma unroll
                    for (int nt = 0; nt < 4; nt++) {
                        float* c = acc[mt*4 + nt];
                        asm volatile(
                            "mma.sync.aligned.m16n8k16.row.col.f32.bf16.bf16.f32 "
                            "{%0,%1,%2,%3}, {%4,%5,%6,%7}, {%8,%9}, {%0,%1,%2,%3};"
                            : "+f"(c[0]), "+f"(c[1]), "+f"(c[2]), "+f"(c[3])
                            : "r"(af[mt][0]), "r"(af[mt][1]), "r"(af[mt][2]), "r"(af[mt][3]),
                              "r"(bfr[nt][0]), "r"(bfr[nt][1]));
                    }
            }
            if (t + 1 < ntiles) storeTile(buf ^ 1);
            __syncthreads();
        }
    }

    const int g = lane >> 2, t = lane & 3;
    bf16* C = Cbase + (long)z * strideC;
    #pragma unroll
    for (int mt = 0; mt < 4; mt++) {
        #pragma unroll
        for (int half = 0; half < 2; half++) {
            int mrow = m0 + wm + mt*16 + g + half*8;
            float bi = RELU ? bias[jj*128 + ((wm + mt*16 + g + half*8) & 127)] : 0.f;
            #pragma unroll
            for (int nt = 0; nt < 4; nt++) {
                float v0 = acc[mt*4 + nt][half*2 + 0] + bi;
                float v1 = acc[mt*4 + nt][half*2 + 1] + bi;
                if (RELU) { v0 = fmaxf(v0, 0.f); v1 = fmaxf(v1, 0.f); }
                int col = n0 + wn + nt*8 + t*2;
                *(unsigned*)&C[(size_t)mrow * ldc + col] = packbf(v0, v1);
            }
        }
    }
}

// ---------------- per-tile max |D16| -> activity flags ----------------
__global__ __launch_bounds__(256) void k_tilemax() {
    int tile = blockIdx.x;
    int nt = tile & 31, r = tile >> 5;
    int kt = r & 15, b = r >> 4;
    const bf16* base = g_D16 + (size_t)b*2097152 + (size_t)kt*32*4096 + nt*128;
    int tid = threadIdx.x;
    int kr = tid >> 3, c0 = (tid & 7) * 16;
    const uint4* p = (const uint4*)(base + (size_t)kr*4096 + c0);
    uint4 u0 = p[0], u1 = p[1];
    unsigned ws[8] = {u0.x, u0.y, u0.z, u0.w, u1.x, u1.y, u1.z, u1.w};
    unsigned mx = 0;
    #pragma unroll
    for (int e = 0; e < 8; e++) {
        unsigned lo = ws[e] & 0x7fffu, hi = (ws[e] >> 16) & 0x7fffu;
        mx = max(mx, max(lo, hi));
    }
    mx = __reduce_max_sync(0xffffffffu, mx);
    __shared__ unsigned sm[8];
    if ((tid & 31) == 0) sm[tid >> 5] = mx;
    __syncthreads();
    if (tid == 0) {
        unsigned m = 0;
        #pragma unroll
        for (int w = 0; w < 8; w++) m = max(m, sm[w]);
        unsigned flags = 0;
        #pragma unroll
        for (int j = 0; j < 4; j++)
            if (m >= g_thrbits[j]) flags |= (1u << j);
        g_tflags[tile] = (unsigned char)flags;
    }
}

// ---------------- bf16 radix select ----------------
__global__ __launch_bounds__(256) void k_histA() {
    __shared__ unsigned sh[256];
    int tid = threadIdx.x;
    sh[tid] = 0u;
    __syncthreads();
    const uint4* __restrict__ src = (const uint4*)g_D16;
    int idx = blockIdx.x * 256 + tid;
    const int stride = gridDim.x * 256;
    const int lane = tid & 31;
    for (int i = idx; i < TOTAL/8; i += stride) {
        uint4 u = src[i];
        unsigned w[4] = {u.x, u.y, u.z, u.w};
        #pragma unroll
        for (int e = 0; e < 4; e++) {
            unsigned lo = (w[e] & 0x7fffu) >> 7;
            unsigned hi = ((w[e] >> 16) & 0x7fffu) >> 7;
            unsigned mm = __match_any_sync(0xffffffffu, lo);
            if (lane == __ffs(mm) - 1) atomicAdd(&sh[lo], (unsigned)__popc(mm));
            mm = __match_any_sync(0xffffffffu, hi);
            if (lane == __ffs(mm) - 1) atomicAdd(&sh[hi], (unsigned)__popc(mm));
        }
    }
    __syncthreads();
    if (sh[tid]) atomicAdd(&g_hist[tid], sh[tid]);
}

__global__ void k_scanA() {
    int j = threadIdx.x;
    if (j < 4) {
        unsigned krem = g_remain[j];
        unsigned cum = 0; int chosen = 0;
        for (int b = 255; b >= 0; b--) {
            unsigned hv = g_hist[b];
            if (cum + hv >= krem) { chosen = b; break; }
            cum += hv;
        }
        g_remain[j] = krem - cum;
        g_prefix[j] = (unsigned)chosen;
    }
    __syncthreads();
    for (int i = threadIdx.x; i < 1024; i += blockDim.x) g_hist[i] = 0u;
}

__global__ __launch_bounds__(256) void k_histB() {
    __shared__ unsigned sh[4][128];
    int tid = threadIdx.x;
    for (int i = tid; i < 512; i += 256) ((unsigned*)sh)[i] = 0u;
    __syncthreads();
    unsigned ph[4];
    #pragma unroll
    for (int j = 0; j < 4; j++) ph[j] = g_prefix[j];
    const uint4* __restrict__ src = (const uint4*)g_D16;
    int idx = blockIdx.x * 256 + tid;
    const int stride = gridDim.x * 256;
    for (int i = idx; i < TOTAL/8; i += stride) {
        uint4 u = src[i];
        unsigned w[4] = {u.x, u.y, u.z, u.w};
        #pragma unroll
        for (int e = 0; e < 4; e++) {
            #pragma unroll
            for (int h = 0; h < 2; h++) {
                unsigned mag = ((h ? (w[e] >> 16) : w[e]) & 0x7fffu);
                unsigned hi = mag >> 7, lo = mag & 127u;
                #pragma unroll
                for (int j = 0; j < 4; j++)
                    if (hi == ph[j]) atomicAdd(&sh[j][lo], 1u);
            }
        }
    }
    __syncthreads();
    for (int i = tid; i < 512; i += 256) {
        unsigned v = ((unsigned*)sh)[i];
        if (v) atomicAdd(&g_hist[i], v);
    }
}

__global__ void k_scanB() {
    int j = threadIdx.x;
    if (j < 4) {
        unsigned krem = g_remain[j];
        const unsigned* h = &g_hist[j*128];
        unsigned cum = 0; int chosen = 0;
        for (int b = 127; b >= 0; b--) {
            unsigned hv = h[b];
            if (cum + hv >= krem) { chosen = b; break; }
            cum += hv;
        }
        g_thrbits[j] = (g_prefix[j] << 7) | (unsigned)chosen;
    }
}

// ---------------- single-read softmax + residual (64KB smem tile) ----------------
__global__ __launch_bounds__(256) void k_final(const float* __restrict__ x, float* __restrict__ out) {
    extern __shared__ unsigned ss[];      // 16384 uints: [c][mnp(32)] = 2 bf16 each
    __shared__ float spart[4][64];
    __shared__ float sinv[64];
    const int tid = threadIdx.x;
    const int b = blockIdx.x >> 6;
    const int mn0 = (blockIdx.x & 63) * 64;
    const int obase = b * 524288 + mn0;
    #pragma unroll
    for (int i = 0; i < 64; i++) {
        int e = i*256 + tid;
        int c = e >> 5, mnp = e & 31;
        ss[c*32 + mnp] = *(const unsigned*)&g_OUTS16[(size_t)(c >> 7) * 4194304 + obase
                                                     + (c & 127) * 4096 + mnp*2];
    }
    __syncthreads();
    {
        int sub = tid >> 6, mn = tid & 63;
        float s = 0.f;
        #pragma unroll 4
        for (int cc = 0; cc < 128; cc++) {
            int c = sub*128 + cc;
            unsigned w = ss[c*32 + (mn >> 1)];
            unsigned short h = (unsigned short)((mn & 1) ? (w >> 16) : (w & 0xffffu));
            s += fexp(__bfloat162float(__ushort_as_bfloat16(h)));
        }
        spart[sub][mn] = s;
    }
    __syncthreads();
    if (tid < 64)
        sinv[tid] = 1.f / (spart[0][tid] + spart[1][tid] + spart[2][tid] + spart[3][tid]);
    __syncthreads();
    {
        int mn = tid & 63, c0 = tid >> 6;
        float inv = sinv[mn];
        const size_t xb = (size_t)b * 2097152 + mn0 + mn;
        #pragma unroll 4
        for (int k = 0; k < 128; k++) {
            int c = c0 + k*4;
            unsigned w = ss[c*32 + (mn >> 1)];
            unsigned short h = (unsigned short)((mn & 1) ? (w >> 16) : (w & 0xffffu));
            float v = __bfloat162float(__ushort_as_bfloat16(h));
            float wt = fexp(v) * inv;
            float xv = x[xb + (size_t)c * 4096];
            out[xb + (size_t)c * 4096] = fmaf(xv, wt, xv);
        }
    }
}

extern "C" void kernel_launch(void* const* d_in, const int* in_sizes, int n_in,
                              void* d_out, int out_size) {
    const float* x  = (const float*)d_in[0];
    const float* W1 = (const float*)d_in[1];
    const float* b1 = (const float*)d_in[2];
    const float* W2 = (const float*)d_in[3];
    const float* b2 = (const float*)d_in[4];
    const float* W3 = (const float*)d_in[5];
    const float* b3 = (const float*)d_in[6];
    float* out = (float*)d_out;

    bf16 *gT16, *gD16, *gM1b, *gH1pre, *gH1, *gH2, *gOUTS16;
    bf16 *gAk16, *gAkI, *gAc16, *gAcT16, *gW1b, *gW2b, *gW3b;
    cudaGetSymbolAddress((void**)&gT16, g_T16);
    cudaGetSymbolAddress((void**)&gD16, g_D16);
    cudaGetSymbolAddress((void**)&gM1b, g_M1b);
    cudaGetSymbolAddress((void**)&gH1pre, g_H1pre);
    cudaGetSymbolAddress((void**)&gH1, g_H1);
    cudaGetSymbolAddress((void**)&gH2, g_H2);
    cudaGetSymbolAddress((void**)&gOUTS16, g_OUTS16);
    cudaGetSymbolAddress((void**)&gAk16, g_Ak16);
    cudaGetSymbolAddress((void**)&gAkI, g_AkI16);
    cudaGetSymbolAddress((void**)&gAc16, g_Ac16);
    cudaGetSymbolAddress((void**)&gAcT16, g_AcT16);
    cudaGetSymbolAddress((void**)&gW1b, g_W1b);
    cudaGetSymbolAddress((void**)&gW2b, g_W2b);
    cudaGetSymbolAddress((void**)&gW3b, g_W3b);

    cudaFuncSetAttribute(k_dct64_tc<1,0>, cudaFuncAttributeMaxDynamicSharedMemorySize, DCT_SMEM);
    cudaFuncSetAttribute(k_dct64_tc<0,1>, cudaFuncAttributeMaxDynamicSharedMemorySize, DCT_SMEM);
    cudaFuncSetAttribute(k_final, cudaFuncAttributeMaxDynamicSharedMemorySize, FINAL_SMEM);

    k_init<<<1, 256>>>();
    k_build_mats<<<1024, 256>>>();

    // forward: MN DCT then C-DCT -> D16 (fwd GEMM at the profiled launch slot)
    k_dct64_tc<1,0><<<2048, 256, DCT_SMEM>>>(x, gT16, gAc16, gAcT16, nullptr);
    k_bgemm<0,0,0,5,1><<<dim3(32,4,8), 256>>>(gAk16, 0L, gT16, 2097152L, 4096, gD16, 2097152L, 4096, 512, nullptr);

    k_cvt_all<<<3584, 256>>>(W1, W2, W3);
    // M1[j] = W1[j] @ AkI
    k_bgemm<0,0,0,0,0><<<dim3(4,1,4), 256>>>(gW1b, 65536L, gAkI, 0L, 512, gM1b, 65536L, 512, 512, nullptr);

    // 2-pass bf16 radix select + tile flags
    k_histA<<<512, 256>>>(); k_scanA<<<1, 256>>>();
    k_histB<<<512, 256>>>(); k_scanB<<<1, 4>>>();
    k_tilemax<<<4096, 256>>>();

    // masked inverse-C fused with conv1 -> H1pre ; spatial inverse + bias1/relu -> H1
    k_bgemm<1,0,0,3,1><<<dim3(32,1,32), 256>>>(gM1b, 65536L, gD16, 2097152L, 4096, gH1pre, 524288L, 4096, 512, nullptr);
    k_dct64_tc<0,1><<<2048, 256, DCT_SMEM>>>(gH1pre, gH1, gAcT16, gAc16, b1);
    // conv2 (im2col fused) and conv3
    k_bgemm<0,1,1,3,0><<<dim3(32,1,32), 256>>>(gW2b, 147456L, gH1, 524288L, 4096, gH2, 524288L, 4096, 1152, b2);
    k_bgemm<0,1,0,3,0><<<dim3(32,1,32), 256>>>(gW3b, 16384L, gH2, 524288L, 4096, gOUTS16, 524288L, 4096, 128, b3);

    k_final<<<512, 256, FINAL_SMEM>>>(x, out);
}

// round 16
// speedup vs baseline: 1.4221x; 1.0480x over previous
#include <cuda_runtime.h>
#include <cuda_bf16.h>
#include <math.h>

typedef __nv_bfloat16 bf16;
#define TOTAL 16777216
#define PI_F 3.14159265358979f
#define DCT_SMEM 55296
#define FINAL_SMEM 65536

__device__ bf16  g_Ac16[64*64];
__device__ bf16  g_AcT16[64*64];
__device__ bf16  g_Ak16[512*512];
__device__ bf16  g_AkI16[512*512];
__device__ bf16  g_T16[TOTAL];
__device__ bf16  g_D16[TOTAL];
__device__ bf16  g_M1b[4*128*512];
__device__ bf16  g_H1pre[32*128*4096];
__device__ bf16  g_H1[32*128*4096];
__device__ bf16  g_H2[32*128*4096];
__device__ bf16  g_OUTS16[TOTAL];
__device__ bf16  g_W1b[4*128*512];
__device__ bf16  g_W2b[4*128*1152];
__device__ bf16  g_W3b[4*128*128];
__device__ unsigned g_hist[1024];
__device__ unsigned g_prefix[4];
__device__ unsigned g_remain[4];
__device__ unsigned g_thrbits[4];
__device__ unsigned g_tmax[4096];          // per-(b,ktile,ntile) max |D16| bits
__device__ unsigned char g_tflags[4096];

__device__ __forceinline__ unsigned packbf(float a, float b) {
    return (unsigned)__bfloat16_as_ushort(__float2bfloat16(a))
         | ((unsigned)__bfloat16_as_ushort(__float2bfloat16(b)) << 16);
}
__device__ __forceinline__ float fexp(float v) {
    float t = v * 1.44269504f;
    int i = (int)t;
    float f = t - (float)i;
    float p = 1.8775767e-3f;
    p = fmaf(p, f, 8.9893397e-3f);
    p = fmaf(p, f, 5.5826318e-2f);
    p = fmaf(p, f, 2.4015361e-1f);
    p = fmaf(p, f, 6.9315307e-1f);
    p = fmaf(p, f, 9.9999989e-1f);
    return p * __int_as_float((i + 127) << 23);
}
__device__ __forceinline__ unsigned smem_u32(const void* p) {
    return (unsigned)__cvta_generic_to_shared(p);
}

__global__ void k_init() {
    int t = blockIdx.x * 256 + threadIdx.x;
    if (t < 4) { g_prefix[t] = 0u; g_remain[t] = (unsigned)(TOTAL >> (2 + 2*t)); }
    if (t < 1024) g_hist[t] = 0u;
    if (t < 4096) g_tmax[t] = 0u;
}

__global__ void k_build_mats() {
    int tid = blockIdx.x * blockDim.x + threadIdx.x;
    if (tid < 512*512) {
        int k = tid >> 9, c = tid & 511;
        float v = cosf((float)k * ((float)c + 0.5f) * (PI_F/512.0f)) * 0.0625f;
        if (k == 0) v *= 0.70710678f;
        g_Ak16[k*512 + c]  = __float2bfloat16(v);
        g_AkI16[c*512 + k] = __float2bfloat16(v);
    }
    if (tid < 4096) {
        int k = tid >> 6, n = tid & 63;
        float v = cosf((float)k * ((float)n + 0.5f) * (PI_F/64.0f)) * 0.1767767f;
        if (k == 0) v *= 0.70710678f;
        bf16 f = __float2bfloat16(v);
        g_Ac16[k*64 + n]  = f;
        g_AcT16[n*64 + k] = f;
    }
}

__global__ void k_cvt_all(const float* __restrict__ W1, const float* __restrict__ W2,
                          const float* __restrict__ W3) {
    int i = blockIdx.x * blockDim.x + threadIdx.x;
    if (i < 262144) {
        g_W1b[i] = __float2bfloat16(W1[i]);
    } else if (i < 262144 + 589824) {
        int q = i - 262144;
        int tap = q % 9;
        int r = q / 9;
        int c = r & 127; r >>= 7;
        int o = r & 127; int j = r >> 7;
        g_W2b[((j*128 + o)*1152) + tap*128 + c] = __float2bfloat16(W2[q]);
    } else if (i < 262144 + 589824 + 65536) {
        int q = i - 262144 - 589824;
        g_W3b[q] = __float2bfloat16(W3[q]);
    }
}

// ---------------- tensor-core fused 64x64 two-sided DCT ----------------
template<int FP32IN, int BIASRELU>
__global__ __launch_bounds__(256) void k_dct64_tc(
    const void* __restrict__ vin, bf16* __restrict__ out,
    const bf16* __restrict__ A1g, const bf16* __restrict__ A2g,
    const float* __restrict__ bias)
{
    extern __shared__ bf16 sm[];
    const int tid = threadIdx.x;
    #pragma unroll
    for (int it = 0; it < 4; it++) {
        int f = it*256 + tid;
        int mat = f >> 9, wf = f & 511;
        int row = wf >> 3, colb = (wf & 7) * 8;
        uint4 v = *(const uint4*)((mat ? A2g : A1g) + row*64 + colb);
        *(uint4*)&sm[mat*4608 + row*72 + colb] = v;
    }
    if (FP32IN) {
        const float* xin = (const float*)vin;
        #pragma unroll
        for (int it = 0; it < 8; it++) {
            int f = it*256 + tid;
            int s = f >> 10, wf = f & 1023;
            int row = wf >> 4, colf = (wf & 15) * 4;
            float4 v = *(const float4*)(xin + (size_t)(blockIdx.x*2 + s)*4096 + row*64 + colf);
            *(uint2*)&sm[9216 + s*4608 + row*72 + colf] =
                make_uint2(packbf(v.x, v.y), packbf(v.z, v.w));
        }
    } else {
        const bf16* yin = (const bf16*)vin;
        #pragma unroll
        for (int it = 0; it < 4; it++) {
            int f = it*256 + tid;
            int s = f >> 9, wf = f & 511;
            int row = wf >> 3, colb = (wf & 7) * 8;
            uint4 v = *(const uint4*)(yin + (size_t)(blockIdx.x*2 + s)*4096 + row*64 + colb);
            *(uint4*)&sm[9216 + s*4608 + row*72 + colb] = v;
        }
    }
    __syncthreads();

    const int warp = tid >> 5, lane = tid & 31;
    const int s = warp >> 2, wrow = (warp & 3) * 16;
    const int slice = blockIdx.x*2 + s;
    float bi = 0.f;
    if (BIASRELU) bi = bias[(slice >> 10)*128 + (slice & 127)];
    bf16* mX = sm + 9216 + s*4608;
    bf16* mQ = sm + 18432 + s*4608;
    const int quad = lane >> 3, qr = lane & 7;
    const int a_moff = (quad & 1)*8 + qr;
    const int a_koff = (quad >> 1)*8;
    const int b_koff = lane & 15;
    const int g = lane >> 2, t4 = lane & 3;

    float acc[8][4];
    unsigned afA[4][4];

    #pragma unroll
    for (int i = 0; i < 8; i++) { acc[i][0]=0.f; acc[i][1]=0.f; acc[i][2]=0.f; acc[i][3]=0.f; }
    #pragma unroll
    for (int kk = 0; kk < 4; kk++) {
        unsigned addr = smem_u32(&sm[(wrow + a_moff)*72 + kk*16 + a_koff]);
        asm volatile("ldmatrix.sync.aligned.m8n8.x4.shared.b16 {%0,%1,%2,%3}, [%4];"
            : "=r"(afA[kk][0]), "=r"(afA[kk][1]), "=r"(afA[kk][2]), "=r"(afA[kk][3]) : "r"(addr));
    }
    #pragma unroll
    for (int kk = 0; kk < 4; kk++)
        #pragma unroll
        for (int nt = 0; nt < 8; nt++) {
            unsigned b0, b1;
            unsigned addr = smem_u32(&mX[(kk*16 + b_koff)*72 + nt*8]);
            asm volatile("ldmatrix.sync.aligned.m8n8.x2.trans.shared.b16 {%0,%1}, [%2];"
                : "=r"(b0), "=r"(b1) : "r"(addr));
            float* c = acc[nt];
            asm volatile(
                "mma.sync.aligned.m16n8k16.row.col.f32.bf16.bf16.f32 "
                "{%0,%1,%2,%3}, {%4,%5,%6,%7}, {%8,%9}, {%0,%1,%2,%3};"
                : "+f"(c[0]), "+f"(c[1]), "+f"(c[2]), "+f"(c[3])
                : "r"(afA[kk][0]), "r"(afA[kk][1]), "r"(afA[kk][2]), "r"(afA[kk][3]),
                  "r"(b0), "r"(b1));
        }
    #pragma unroll
    for (int nt = 0; nt < 8; nt++)
        #pragma unroll
        for (int h = 0; h < 2; h++) {
            int row = wrow + g + h*8, col = nt*8 + t4*2;
            *(unsigned*)&mQ[row*72 + col] = packbf(acc[nt][h*2], acc[nt][h*2+1]);
        }
    __syncwarp();

    #pragma unroll
    for (int i = 0; i < 8; i++) { acc[i][0]=0.f; acc[i][1]=0.f; acc[i][2]=0.f; acc[i][3]=0.f; }
    #pragma unroll
    for (int kk = 0; kk < 4; kk++) {
        unsigned addr = smem_u32(&mQ[(wrow + a_moff)*72 + kk*16 + a_koff]);
        asm volatile("ldmatrix.sync.aligned.m8n8.x4.shared.b16 {%0,%1,%2,%3}, [%4];"
            : "=r"(afA[kk][0]), "=r"(afA[kk][1]), "=r"(afA[kk][2]), "=r"(afA[kk][3]) : "r"(addr));
    }
    #pragma unroll
    for (int kk = 0; kk < 4; kk++)
        #pragma unroll
        for (int nt = 0; nt < 8; nt++) {
            unsigned b0, b1;
            unsigned addr = smem_u32(&sm[4608 + (kk*16 + b_koff)*72 + nt*8]);
            asm volatile("ldmatrix.sync.aligned.m8n8.x2.trans.shared.b16 {%0,%1}, [%2];"
                : "=r"(b0), "=r"(b1) : "r"(addr));
            float* c = acc[nt];
            asm volatile(
                "mma.sync.aligned.m16n8k16.row.col.f32.bf16.bf16.f32 "
                "{%0,%1,%2,%3}, {%4,%5,%6,%7}, {%8,%9}, {%0,%1,%2,%3};"
                : "+f"(c[0]), "+f"(c[1]), "+f"(c[2]), "+f"(c[3])
                : "r"(afA[kk][0]), "r"(afA[kk][1]), "r"(afA[kk][2]), "r"(afA[kk][3]),
                  "r"(b0), "r"(b1));
        }
    bf16* dst = out + (size_t)slice*4096;
    #pragma unroll
    for (int nt = 0; nt < 8; nt++)
        #pragma unroll
        for (int h = 0; h < 2; h++) {
            int row = wrow + g + h*8, col = nt*8 + t4*2;
            float v0 = acc[nt][h*2], v1 = acc[nt][h*2+1];
            if (BIASRELU) { v0 = fmaxf(v0 + bi, 0.f); v1 = fmaxf(v1 + bi, 0.f); }
            *(unsigned*)&dst[row*64 + col] = packbf(v0, v1);
        }
}

// ---------------- bf16 mma.sync GEMM ----------------
// STATS: fused 256-bin |value| histogram + per-(kt,nt)-tile max (for the select path)
template<int MASKED, int RELU, int IM2COL, int ZDIV, int BMOD8, int STATS>
__global__ __launch_bounds__(256) void k_bgemm(
    const bf16* __restrict__ Abase, long strideAj,
    const bf16* __restrict__ Bbase, long strideB, int ldb,
    bf16* __restrict__ Cbase, long strideC, int ldc,
    int K, const float* __restrict__ bias)
{
    __shared__ bf16 sA[2][128*40];
    __shared__ bf16 sB[2][32*136];
    __shared__ unsigned char s_klist[16];
    __shared__ int s_kn;
    __shared__ unsigned shist[256];
    const int tid = threadIdx.x;
    const int warp = tid >> 5, lane = tid & 31;
    const int z = blockIdx.z;
    const int jj = z >> ZDIV;
    const int zb = BMOD8 ? (z & 7) : z;
    const bf16* __restrict__ A = Abase + (long)jj * strideAj;
    const bf16* __restrict__ B = Bbase + (long)zb * strideB;
    const int m0 = blockIdx.y << 7, n0 = blockIdx.x << 7;
    const int wm = (warp >> 2) * 64;
    const int wn = (warp & 3) * 32;
    const unsigned thr = MASKED ? g_thrbits[jj] : 0u;

    if (STATS) shist[tid] = 0u;
    if (MASKED) {
        if (tid == 0) {
            int cnt = 0;
            int base = zb*512 + (n0 >> 7);
            for (int kt = 0; kt < 16; kt++)
                if (g_tflags[base + kt*32] & (1u << jj)) s_klist[cnt++] = (unsigned char)kt;
            s_kn = cnt;
        }
        __syncthreads();
    }

    const int quad = lane >> 3, qr = lane & 7;
    const int a_moff = (quad & 1) * 8 + qr;
    const int a_koff = (quad >> 1) * 8;
    const int b_koff = lane & 15;

    const int a_r = tid >> 2;
    const int a_kg = (tid & 3) * 8;
    const int b_kr = tid >> 3;
    const int b_ng = (tid & 7) * 16;

    float acc[16][4];
    #pragma unroll
    for (int i = 0; i < 16; i++) { acc[i][0]=0.f; acc[i][1]=0.f; acc[i][2]=0.f; acc[i][3]=0.f; }

    uint4 rA0, rA1, rB0, rB1;

    auto loadTile = [&](int k0) {
        rA0 = *(const uint4*)&A[(size_t)(m0 + a_r) * K + k0 + a_kg];
        rA1 = *(const uint4*)&A[(size_t)(m0 + a_r + 64) * K + k0 + a_kg];
        if (!IM2COL) {
            int krow = k0 + b_kr;
            const bf16* bp = &B[(size_t)krow * ldb + n0 + b_ng];
            rB0 = *(const uint4*)bp;
            rB1 = *(const uint4*)(bp + 8);
            if (MASKED) {
                unsigned short* s0 = (unsigned short*)&rB0;
                unsigned short* s1 = (unsigned short*)&rB1;
                #pragma unroll
                for (int e = 0; e < 8; e++) {
                    if ((unsigned)(s0[e] & 0x7fff) < thr) s0[e] = 0;
                    if ((unsigned)(s1[e] & 0x7fff) < thr) s1[e] = 0;
                }
            }
        } else {
            int k = k0 + b_kr;
            int tap = k >> 7;
            int c = k & 127;
            int t3 = tap / 3;
            int dy = 2*t3 - 2;
            int dx = 2*(tap - 3*t3) - 2;
            int mn0 = n0 + b_ng;
            int m = mn0 >> 6, n = mn0 & 63;
            int mp = m + dy;
            bool mok = ((unsigned)mp < 64u);
            const bf16* row = &B[(size_t)c * 4096 + mp * 64];
            uint4 a0 = make_uint4(0,0,0,0), a1 = make_uint4(0,0,0,0);
            unsigned e = 0;
            if (mok) {
                a0 = *(const uint4*)&row[n];
                a1 = *(const uint4*)&row[n + 8];
                if (dx == 2)       { if (n + 16 < 64) e = *(const unsigned*)&row[n + 16]; }
                else if (dx == -2) { if (n > 0)       e = *(const unsigned*)&row[n - 2]; }
            }
            if (dx == 0)      { rB0 = a0; rB1 = a1; }
            else if (dx == 2) { rB0 = make_uint4(a0.y, a0.z, a0.w, a1.x);
                                rB1 = make_uint4(a1.y, a1.z, a1.w, e); }
            else              { rB0 = make_uint4(e, a0.x, a0.y, a0.z);
                                rB1 = make_uint4(a0.w, a1.x, a1.y, a1.z); }
        }
    };
    auto storeTile = [&](int buf) {
        *(uint4*)&sA[buf][a_r*40 + a_kg]        = rA0;
        *(uint4*)&sA[buf][(a_r + 64)*40 + a_kg] = rA1;
        *(uint4*)&sB[buf][b_kr*136 + b_ng]      = rB0;
        *(uint4*)&sB[buf][b_kr*136 + b_ng + 8]  = rB1;
    };

    const int ntiles = MASKED ? s_kn : (K >> 5);
    if (ntiles > 0) {
        loadTile(MASKED ? ((int)s_klist[0] << 5) : 0);
        storeTile(0);
        __syncthreads();
        for (int t = 0; t < ntiles; t++) {
            const int buf = t & 1;
            if (t + 1 < ntiles)
                loadTile(MASKED ? ((int)s_klist[t + 1] << 5) : ((t + 1) << 5));
            #pragma unroll
            for (int kk = 0; kk < 32; kk += 16) {
                unsigned af[4][4], bfr[4][2];
                #pragma unroll
                for (int mt = 0; mt < 4; mt++) {
                    unsigned addr = smem_u32(&sA[buf][(wm + mt*16 + a_moff)*40 + kk + a_koff]);
                    asm volatile("ldmatrix.sync.aligned.m8n8.x4.shared.b16 {%0,%1,%2,%3}, [%4];"
                        : "=r"(af[mt][0]), "=r"(af[mt][1]), "=r"(af[mt][2]), "=r"(af[mt][3])
                        : "r"(addr));
                }
                #pragma unroll
                for (int nt = 0; nt < 4; nt++) {
                    unsigned addr = smem_u32(&sB[buf][(kk + b_koff)*136 + wn + nt*8]);
                    asm volatile("ldmatrix.sync.aligned.m8n8.x2.trans.shared.b16 {%0,%1}, [%2];"
                        : "=r"(bfr[nt][0]), "=r"(bfr[nt][1]) : "r"(addr));
                }
                #pragma unroll
                for (int mt = 0; mt < 4; mt++)
                    #pragma unroll
                    for (int nt = 0; nt < 4; nt++) {
                        float* c = acc[mt*4 + nt];
                        asm volatile(
                            "mma.sync.aligned.m16n8k16.row.col.f32.bf16.bf16.f32 "
                            "{%0,%1,%2,%3}, {%4,%5,%6,%7}, {%8,%9}, {%0,%1,%2,%3};"
                            : "+f"(c[0]), "+f"(c[1]), "+f"(c[2]), "+f"(c[3])
                            : "r"(af[mt][0]), "r"(af[mt][1]), "r"(af[mt][2]), "r"(af[mt][3]),
                              "r"(bfr[nt][0]), "r"(bfr[nt][1]));
                    }
            }
            if (t + 1 < ntiles) storeTile(buf ^ 1);
            __syncthreads();
        }
    }

    const int g = lane >> 2, t = lane & 3;
    bf16* C = Cbase + (long)z * strideC;
    #pragma unroll
    for (int mt = 0; mt < 4; mt++) {
        unsigned wmax = 0u;
        #pragma unroll
        for (int half = 0; half < 2; half++) {
            int mrow = m0 + wm + mt*16 + g + half*8;
            float bi = RELU ? bias[jj*128 + ((wm + mt*16 + g + half*8) & 127)] : 0.f;
            #pragma unroll
            for (int nt = 0; nt < 4; nt++) {
                float v0 = acc[mt*4 + nt][half*2 + 0] + bi;
                float v1 = acc[mt*4 + nt][half*2 + 1] + bi;
                if (RELU) { v0 = fmaxf(v0, 0.f); v1 = fmaxf(v1, 0.f); }
                int col = n0 + wn + nt*8 + t*2;
                unsigned pk = packbf(v0, v1);
                *(unsigned*)&C[(size_t)mrow * ldc + col] = pk;
                if (STATS) {
                    unsigned lo = pk & 0x7fffu, hi = (pk >> 16) & 0x7fffu;
                    wmax = max(wmax, max(lo, hi));
                    unsigned b0 = lo >> 7, b1h = hi >> 7;
                    unsigned mm = __match_any_sync(0xffffffffu, b0);
                    if (lane == __ffs(mm) - 1) atomicAdd(&shist[b0], (unsigned)__popc(mm));
                    mm = __match_any_sync(0xffffffffu, b1h);
                    if (lane == __ffs(mm) - 1) atomicAdd(&shist[b1h], (unsigned)__popc(mm));
                }
            }
        }
        if (STATS) {
            wmax = __reduce_max_sync(0xffffffffu, wmax);
            if (lane == 0) {
                int ktg = (m0 + wm + mt*16) >> 5;
                atomicMax(&g_tmax[zb*512 + ktg*32 + (n0 >> 7)], wmax);
            }
        }
    }
    if (STATS) {
        __syncthreads();
        if (shist[tid]) atomicAdd(&g_hist[tid], shist[tid]);
    }
}

// ---------------- select scans + flags ----------------
__global__ void k_scanA() {
    int j = threadIdx.x;
    if (j < 4) {
        unsigned krem = g_remain[j];
        unsigned cum = 0; int chosen = 0;
        for (int b = 255; b >= 0; b--) {
            unsigned hv = g_hist[b];
            if (cum + hv >= krem) { chosen = b; break; }
            cum += hv;
        }
        g_remain[j] = krem - cum;
        g_prefix[j] = (unsigned)chosen;
    }
    __syncthreads();
    for (int i = threadIdx.x; i < 1024; i += blockDim.x) g_hist[i] = 0u;
}

__global__ __launch_bounds__(256) void k_histB() {
    __shared__ unsigned sh[4][128];
    int tid = threadIdx.x;
    for (int i = tid; i < 512; i += 256) ((unsigned*)sh)[i] = 0u;
    __syncthreads();
    unsigned ph[4];
    #pragma unroll
    for (int j = 0; j < 4; j++) ph[j] = g_prefix[j];
    const uint4* __restrict__ src = (const uint4*)g_D16;
    int idx = blockIdx.x * 256 + tid;
    const int stride = gridDim.x * 256;
    for (int i = idx; i < TOTAL/8; i += stride) {
        uint4 u = src[i];
        unsigned w[4] = {u.x, u.y, u.z, u.w};
        #pragma unroll
        for (int e = 0; e < 4; e++) {
            #pragma unroll
            for (int h = 0; h < 2; h++) {
                unsigned mag = ((h ? (w[e] >> 16) : w[e]) & 0x7fffu);
                unsigned hi = mag >> 7, lo = mag & 127u;
                #pragma unroll
                for (int j = 0; j < 4; j++)
                    if (hi == ph[j]) atomicAdd(&sh[j][lo], 1u);
            }
        }
    }
    __syncthreads();
    for (int i = tid; i < 512; i += 256) {
        unsigned v = ((unsigned*)sh)[i];
        if (v) atomicAdd(&g_hist[i], v);
    }
}

__global__ void k_scanB() {
    int j = threadIdx.x;
    if (j < 4) {
        unsigned krem = g_remain[j];
        const unsigned* h = &g_hist[j*128];
        unsigned cum = 0; int chosen = 0;
        for (int b = 127; b >= 0; b--) {
            unsigned hv = h[b];
            if (cum + hv >= krem) { chosen = b; break; }
            cum += hv;
        }
        g_thrbits[j] = (g_prefix[j] << 7) | (unsigned)chosen;
    }
}

__global__ void k_flags() {
    int t = blockIdx.x * 256 + threadIdx.x;
    if (t >= 4096) return;
    unsigned m = g_tmax[t];
    unsigned flags = 0;
    #pragma unroll
    for (int j = 0; j < 4; j++)
        if (m >= g_thrbits[j]) flags |= (1u << j);
    g_tflags[t] = (unsigned char)flags;
}

// ---------------- single-read softmax + residual ----------------
__global__ __launch_bounds__(256) void k_final(const float* __restrict__ x, float* __restrict__ out) {
    extern __shared__ unsigned ss[];
    __shared__ float spart[4][64];
    __shared__ float sinv[64];
    const int tid = threadIdx.x;
    const int b = blockIdx.x >> 6;
    const int mn0 = (blockIdx.x & 63) * 64;
    const int obase = b * 524288 + mn0;
    #pragma unroll
    for (int i = 0; i < 64; i++) {
        int e = i*256 + tid;
        int c = e >> 5, mnp = e & 31;
        ss[c*32 + mnp] = *(const unsigned*)&g_OUTS16[(size_t)(c >> 7) * 4194304 + obase
                                                     + (c & 127) * 4096 + mnp*2];
    }
    __syncthreads();
    {
        int sub = tid >> 6, mn = tid & 63;
        float s = 0.f;
        #pragma unroll 4
        for (int cc = 0; cc < 128; cc++) {
            int c = sub*128 + cc;
            unsigned w = ss[c*32 + (mn >> 1)];
            unsigned short h = (unsigned short)((mn & 1) ? (w >> 16) : (w & 0xffffu));
            s += fexp(__bfloat162float(__ushort_as_bfloat16(h)));
        }
        spart[sub][mn] = s;
    }
    __syncthreads();
    if (tid < 64)
        sinv[tid] = 1.f / (spart[0][tid] + spart[1][tid] + spart[2][tid] + spart[3][tid]);
    __syncthreads();
    {
        int mn = tid & 63, c0 = tid >> 6;
        float inv = sinv[mn];
        const size_t xb = (size_t)b * 2097152 + mn0 + mn;
        #pragma unroll 4
        for (int k = 0; k < 128; k++) {
            int c = c0 + k*4;
            unsigned w = ss[c*32 + (mn >> 1)];
            unsigned short h = (unsigned short)((mn & 1) ? (w >> 16) : (w & 0xffffu));
            float v = __bfloat162float(__ushort_as_bfloat16(h));
            float wt = fexp(v) * inv;
            float xv = x[xb + (size_t)c * 4096];
            out[xb + (size_t)c * 4096] = fmaf(xv, wt, xv);
        }
    }
}

extern "C" void kernel_launch(void* const* d_in, const int* in_sizes, int n_in,
                              void* d_out, int out_size) {
    const float* x  = (const float*)d_in[0];
    const float* W1 = (const float*)d_in[1];
    const float* b1 = (const float*)d_in[2];
    const float* W2 = (const float*)d_in[3];
    const float* b2 = (const float*)d_in[4];
    const float* W3 = (const float*)d_in[5];
    const float* b3 = (const float*)d_in[6];
    float* out = (float*)d_out;

    bf16 *gT16, *gD16, *gM1b, *gH1pre, *gH1, *gH2, *gOUTS16;
    bf16 *gAk16, *gAkI, *gAc16, *gAcT16, *gW1b, *gW2b, *gW3b;
    cudaGetSymbolAddress((void**)&gT16, g_T16);
    cudaGetSymbolAddress((void**)&gD16, g_D16);
    cudaGetSymbolAddress((void**)&gM1b, g_M1b);
    cudaGetSymbolAddress((void**)&gH1pre, g_H1pre);
    cudaGetSymbolAddress((void**)&gH1, g_H1);
    cudaGetSymbolAddress((void**)&gH2, g_H2);
    cudaGetSymbolAddress((void**)&gOUTS16, g_OUTS16);
    cudaGetSymbolAddress((void**)&gAk16, g_Ak16);
    cudaGetSymbolAddress((void**)&gAkI, g_AkI16);
    cudaGetSymbolAddress((void**)&gAc16, g_Ac16);
    cudaGetSymbolAddress((void**)&gAcT16, g_AcT16);
    cudaGetSymbolAddress((void**)&gW1b, g_W1b);
    cudaGetSymbolAddress((void**)&gW2b, g_W2b);
    cudaGetSymbolAddress((void**)&gW3b, g_W3b);

    cudaFuncSetAttribute(k_dct64_tc<1,0>, cudaFuncAttributeMaxDynamicSharedMemorySize, DCT_SMEM);
    cudaFuncSetAttribute(k_dct64_tc<0,1>, cudaFuncAttributeMaxDynamicSharedMemorySize, DCT_SMEM);
    cudaFuncSetAttribute(k_final, cudaFuncAttributeMaxDynamicSharedMemorySize, FINAL_SMEM);

    k_init<<<16, 256>>>();
    k_build_mats<<<1024, 256>>>();

    // forward: MN DCT then C-DCT -> D16 with fused histogram + tile-max (slot-3 profile target)
    k_dct64_tc<1,0><<<2048, 256, DCT_SMEM>>>(x, gT16, gAc16, gAcT16, nullptr);
    k_bgemm<0,0,0,5,1,1><<<dim3(32,4,8), 256>>>(gAk16, 0L, gT16, 2097152L, 4096, gD16, 2097152L, 4096, 512, nullptr);

    k_cvt_all<<<3584, 256>>>(W1, W2, W3);
    // M1[j] = W1[j] @ AkI
    k_bgemm<0,0,0,0,0,0><<<dim3(4,1,4), 256>>>(gW1b, 65536L, gAkI, 0L, 512, gM1b, 65536L, 512, 512, nullptr);

    // select: pass-A histogram already accumulated by the fwd GEMM epilogue
    k_scanA<<<1, 256>>>();
    k_histB<<<512, 256>>>(); k_scanB<<<1, 4>>>();
    k_flags<<<16, 256>>>();

    // masked inverse-C fused with conv1 -> H1pre ; spatial inverse + bias1/relu -> H1
    k_bgemm<1,0,0,3,1,0><<<dim3(32,1,32), 256>>>(gM1b, 65536L, gD16, 2097152L, 4096, gH1pre, 524288L, 4096, 512, nullptr);
    k_dct64_tc<0,1><<<2048, 256, DCT_SMEM>>>(gH1pre, gH1, gAcT16, gAc16, b1);
    // conv2 (im2col fused) and conv3
    k_bgemm<0,1,1,3,0,0><<<dim3(32,1,32), 256>>>(gW2b, 147456L, gH1, 524288L, 4096, gH2, 524288L, 4096, 1152, b2);
    k_bgemm<0,1,0,3,0,0><<<dim3(32,1,32), 256>>>(gW3b, 16384L, gH2, 524288L, 4096, gOUTS16, 524288L, 4096, 128, b3);

    k_final<<<512, 256, FINAL_SMEM>>>(x, out);
}